// round 3
// baseline (speedup 1.0000x reference)
#include <cuda_runtime.h>
#include <cuda_bf16.h>
#include <math.h>

// Problem constants
#define NN_MAX 50000
#define NE_MAX 400000
#define DIM 256
#define NHEAD 4

// ---------------- scratch (static __device__ arrays, no allocation) -------
__device__ float    g_node_proj[NN_MAX * 768];   // [q|k|v] per node  (153.6 MB)
__device__ float    g_edge_proj[NE_MAX * 768];   // [q|k|v] per edge  (1.23 GB)
__device__ float    g_scores[NE_MAX * NHEAD];    // scores -> ex (in place)
__device__ unsigned g_m[NN_MAX * NHEAD];         // segment max (ordered-uint)
__device__ float    g_denom[NN_MAX * NHEAD];     // segment sum of exp
__device__ float    g_attn_out[NN_MAX * DIM];    // scatter destination
__device__ float    g_tmp[NN_MAX * DIM];         // after Wo
__device__ float    g_h1[NN_MAX * DIM];          // after LN1
__device__ float    g_ff[NN_MAX * 1024];         // after FFN1+gelu
__device__ float    g_ff2[NN_MAX * DIM];         // after FFN2

// ---------------- helpers --------------------------------------------------
__device__ __forceinline__ unsigned f2o(float f) {
    unsigned u = __float_as_uint(f);
    return (u & 0x80000000u) ? ~u : (u | 0x80000000u);
}
__device__ __forceinline__ float o2f(unsigned u) {
    return __uint_as_float((u & 0x80000000u) ? (u & 0x7fffffffu) : ~u);
}
__device__ __forceinline__ float gelu_exact(float x) {
    return 0.5f * x * (1.0f + erff(x * 0.70710678118654752440f));
}
// packed f32x2 FMA (sm_103a): d = a*b + d  lanewise on two fp32 values
__device__ __forceinline__ void fma2(unsigned long long& d,
                                     unsigned long long a,
                                     unsigned long long b) {
    asm("fma.rn.f32x2 %0, %1, %2, %0;" : "+l"(d) : "l"(a), "l"(b));
}
__device__ __forceinline__ unsigned long long dup2(float x) {
    unsigned long long r;
    unsigned xi = __float_as_uint(x);
    asm("mov.b64 %0, {%1, %1};" : "=l"(r) : "r"(xi));
    return r;
}

// ---------------- zero scratch --------------------------------------------
__global__ void k_zero(int n_att, int n_md) {
    int i = blockIdx.x * blockDim.x + threadIdx.x;
    if (i < n_att) g_attn_out[i] = 0.0f;
    if (i < n_md) { g_m[i] = 0u; g_denom[i] = 0.0f; }
}

// ---------------- generic SGEMM: C[M,N] = A[M,K] @ W (+bias)(+gelu) -------
// W is split: output cols [0,n0) come from W0 (ld ldw0), cols [n0,N) from W1.
// BN=128 divides n0 boundaries (all are multiples of 128), so each block's
// column tile lives entirely in one weight matrix.
__global__ __launch_bounds__(256)
void sgemm128(const float* __restrict__ A, int M, int K,
              const float* __restrict__ W0, int n0, int ldw0,
              const float* __restrict__ b0,
              const float* __restrict__ W1, int ldw1,
              const float* __restrict__ b1,
              float* __restrict__ C, int N, int act) {
    __shared__ __align__(16) float As[8][128];
    __shared__ __align__(16) float Bs[8][128];

    const int cb = blockIdx.x * 128;
    const int rb = blockIdx.y * 128;

    const float* W; int ldw; const float* bias;
    if (cb < n0) { W = W0 + cb;        ldw = ldw0; bias = b0 ? (b0 + cb)        : nullptr; }
    else         { W = W1 + (cb - n0); ldw = ldw1; bias = b1 ? (b1 + (cb - n0)) : nullptr; }

    const int t  = threadIdx.x;
    const int tx = t & 15;        // 16 column groups of 8
    const int ty = t >> 4;        // 16 row groups of 8
    const int arow = t >> 1;          // 0..127
    const int ak   = (t & 1) * 4;     // 0 or 4
    const int bk   = t >> 5;          // 0..7
    const int bc   = (t & 31) * 4;    // 0..124

    unsigned long long acc[8][4];
#pragma unroll
    for (int i = 0; i < 8; i++)
#pragma unroll
        for (int j = 0; j < 4; j++) acc[i][j] = 0ULL;

    for (int k0 = 0; k0 < K; k0 += 8) {
        // load A tile (128 rows x 8 k), transposed into As[k][row]
        float4 av = make_float4(0.f, 0.f, 0.f, 0.f);
        int gr = rb + arow;
        if (gr < M) av = *(const float4*)(A + (size_t)gr * K + k0 + ak);
        As[ak + 0][arow] = av.x;
        As[ak + 1][arow] = av.y;
        As[ak + 2][arow] = av.z;
        As[ak + 3][arow] = av.w;
        // load B tile (8 k x 128 cols)
        float4 bv = *(const float4*)(W + (size_t)(k0 + bk) * ldw + bc);
        *(float4*)&Bs[bk][bc] = bv;
        __syncthreads();

#pragma unroll
        for (int kk = 0; kk < 8; kk++) {
            float4 a0 = *(const float4*)&As[kk][ty * 8];
            float4 a1 = *(const float4*)&As[kk][ty * 8 + 4];
            const unsigned long long* bp =
                (const unsigned long long*)&Bs[kk][tx * 8];
            unsigned long long b2[4];
#pragma unroll
            for (int jp = 0; jp < 4; jp++) b2[jp] = bp[jp];
            float a[8] = {a0.x, a0.y, a0.z, a0.w, a1.x, a1.y, a1.z, a1.w};
#pragma unroll
            for (int i = 0; i < 8; i++) {
                unsigned long long ad = dup2(a[i]);
#pragma unroll
                for (int jp = 0; jp < 4; jp++) fma2(acc[i][jp], ad, b2[jp]);
            }
        }
        __syncthreads();
    }

    // epilogue
#pragma unroll
    for (int i = 0; i < 8; i++) {
        int r = rb + ty * 8 + i;
        if (r >= M) continue;
        float* crow = C + (size_t)r * N + cb + tx * 8;
#pragma unroll
        for (int jp = 0; jp < 4; jp++) {
            float lo = __uint_as_float((unsigned)(acc[i][jp]));
            float hi = __uint_as_float((unsigned)(acc[i][jp] >> 32));
            if (bias) { lo += bias[tx * 8 + 2 * jp]; hi += bias[tx * 8 + 2 * jp + 1]; }
            if (act == 1) { lo = gelu_exact(lo); hi = gelu_exact(hi); }
            crow[2 * jp]     = lo;
            crow[2 * jp + 1] = hi;
        }
    }
}

// ---------------- per-edge scores + segment max ---------------------------
// one warp per edge; lane l covers elements l+32j, j=0..7; head = j>>1
__global__ void k_scores(const int* __restrict__ ei, int NE) {
    int w = (blockIdx.x * blockDim.x + threadIdx.x) >> 5;
    int lane = threadIdx.x & 31;
    if (w >= NE) return;
    int src = ei[w];
    int dst = ei[NE + w];
    const float* qn = g_node_proj + (size_t)src * 768;
    const float* kn = g_node_proj + (size_t)dst * 768 + 256;
    const float* qe = g_edge_proj + (size_t)w * 768;
    const float* ke = qe + 256;
    float ps[4] = {0.f, 0.f, 0.f, 0.f};
#pragma unroll
    for (int j = 0; j < 8; j++) {
        int i = lane + 32 * j;
        float q = qn[i] + qe[i];
        float k = kn[i] + ke[i];
        ps[j >> 1] += q * k;
    }
#pragma unroll
    for (int h = 0; h < 4; h++)
#pragma unroll
        for (int off = 16; off; off >>= 1)
            ps[h] += __shfl_xor_sync(0xffffffffu, ps[h], off);
    if (lane < 4) {
        float s = ps[lane] * 0.125f;  // 1/sqrt(64)
        g_scores[(size_t)w * 4 + lane] = s;
        atomicMax(&g_m[src * 4 + lane], f2o(s));
    }
}

// ---------------- exp + segment sum ---------------------------------------
__global__ void k_expsum(const int* __restrict__ ei, int NE) {
    int i = blockIdx.x * blockDim.x + threadIdx.x;
    if (i >= NE * 4) return;
    int e = i >> 2, h = i & 3;
    int src = ei[e];
    float m = o2f(g_m[src * 4 + h]);
    float ex = expf(g_scores[i] - m);
    g_scores[i] = ex;
    atomicAdd(&g_denom[src * 4 + h], ex);
}

// ---------------- attn * V scatter ----------------------------------------
__global__ void k_scatter(const int* __restrict__ ei, int NE) {
    int w = (blockIdx.x * blockDim.x + threadIdx.x) >> 5;
    int lane = threadIdx.x & 31;
    if (w >= NE) return;
    int src = ei[w];
    int dst = ei[NE + w];
    float attn[4];
#pragma unroll
    for (int h = 0; h < 4; h++)
        attn[h] = g_scores[(size_t)w * 4 + h] / g_denom[src * 4 + h];
    const float* vn = g_node_proj + (size_t)dst * 768 + 512;
    const float* ve = g_edge_proj + (size_t)w * 768 + 512;
    float* o = g_attn_out + (size_t)src * 256;
#pragma unroll
    for (int j = 0; j < 8; j++) {
        int i = lane + 32 * j;
        float v = vn[i] + ve[i];
        atomicAdd(&o[i], attn[j >> 1] * v);
    }
}

// ---------------- layernorm (warp per row of 256) -------------------------
__global__ void k_ln(const float* __restrict__ x, const float* __restrict__ res,
                     const float* __restrict__ g, const float* __restrict__ b,
                     float* __restrict__ out, int M) {
    int w = (blockIdx.x * blockDim.x + threadIdx.x) >> 5;
    int lane = threadIdx.x & 31;
    if (w >= M) return;
    float v[8];
    float s = 0.f;
#pragma unroll
    for (int j = 0; j < 8; j++) {
        int i = lane + 32 * j;
        v[j] = x[(size_t)w * 256 + i] + res[(size_t)w * 256 + i];
        s += v[j];
    }
#pragma unroll
    for (int off = 16; off; off >>= 1) s += __shfl_xor_sync(0xffffffffu, s, off);
    float mu = s * (1.0f / 256.0f);
    float q = 0.f;
#pragma unroll
    for (int j = 0; j < 8; j++) { float d = v[j] - mu; q += d * d; }
#pragma unroll
    for (int off = 16; off; off >>= 1) q += __shfl_xor_sync(0xffffffffu, q, off);
    float rstd = rsqrtf(q * (1.0f / 256.0f) + 1e-5f);
#pragma unroll
    for (int j = 0; j < 8; j++) {
        int i = lane + 32 * j;
        out[(size_t)w * 256 + i] = (v[j] - mu) * rstd * g[i] + b[i];
    }
}

// ---------------- host launch ----------------------------------------------
extern "C" void kernel_launch(void* const* d_in, const int* in_sizes, int n_in,
                              void* d_out, int out_size) {
    const float* h_n   = (const float*)d_in[0];
    const float* h_e   = (const float*)d_in[1];
    const int*   ei    = (const int*)d_in[2];   // int32! (JAX x64 disabled)
    const float* Wq_w  = (const float*)d_in[3];
    const float* Wq_b  = (const float*)d_in[4];
    const float* Wkv_w = (const float*)d_in[5];
    const float* Wkv_b = (const float*)d_in[6];
    const float* Wo_w  = (const float*)d_in[7];
    const float* Wo_b  = (const float*)d_in[8];
    const float* ln1_g = (const float*)d_in[9];
    const float* ln1_b = (const float*)d_in[10];
    const float* f1w   = (const float*)d_in[11];
    const float* f1b   = (const float*)d_in[12];
    const float* f2w   = (const float*)d_in[13];
    const float* f2b   = (const float*)d_in[14];
    const float* ln2_g = (const float*)d_in[15];
    const float* ln2_b = (const float*)d_in[16];
    float* out = (float*)d_out;

    int NN = in_sizes[0] / DIM;
    int NE = in_sizes[1] / DIM;

    void *p_np, *p_ep, *p_att, *p_tmp, *p_h1, *p_ff, *p_ff2;
    cudaGetSymbolAddress(&p_np, g_node_proj);
    cudaGetSymbolAddress(&p_ep, g_edge_proj);
    cudaGetSymbolAddress(&p_att, g_attn_out);
    cudaGetSymbolAddress(&p_tmp, g_tmp);
    cudaGetSymbolAddress(&p_h1, g_h1);
    cudaGetSymbolAddress(&p_ff, g_ff);
    cudaGetSymbolAddress(&p_ff2, g_ff2);

    // 1. zero segment-max / denom / scatter destination
    {
        int n_att = NN * DIM;
        int n_md = NN * NHEAD;
        int n = n_att > n_md ? n_att : n_md;
        k_zero<<<(n + 255) / 256, 256>>>(n_att, n_md);
    }

    // 2. node projections: [q|k|v] = h_n @ [Wq_top | Wkv_top] + biases
    sgemm128<<<dim3(6, (NN + 127) / 128), 256>>>(
        h_n, NN, 256, Wq_w, 256, 256, Wq_b, Wkv_w, 512, Wkv_b,
        (float*)p_np, 768, 0);

    // 3. edge projections: [q|k|v] = h_e @ [Wq_bot | Wkv_bot]  (no bias)
    sgemm128<<<dim3(6, (NE + 127) / 128), 256>>>(
        h_e, NE, 256, Wq_w + 256 * 256, 256, 256, nullptr,
        Wkv_w + 256 * 512, 512, nullptr,
        (float*)p_ep, 768, 0);

    // 4. per-edge head scores + segment max
    k_scores<<<(NE + 7) / 8, 256>>>(ei, NE);

    // 5. exp + segment sum
    k_expsum<<<(NE * 4 + 255) / 256, 256>>>(ei, NE);

    // 6. attn-weighted V scatter
    k_scatter<<<(NE + 7) / 8, 256>>>(ei, NE);

    // 7. output projection Wo
    sgemm128<<<dim3(2, (NN + 127) / 128), 256>>>(
        (const float*)p_att, NN, 256, Wo_w, 256, 256, Wo_b,
        nullptr, 0, nullptr, (float*)p_tmp, 256, 0);

    // 8. LN1(h_n + attn_proj)
    k_ln<<<(NN + 7) / 8, 256>>>(h_n, (const float*)p_tmp, ln1_g, ln1_b,
                                (float*)p_h1, NN);

    // 9. FFN1 + exact GELU
    sgemm128<<<dim3(8, (NN + 127) / 128), 256>>>(
        (const float*)p_h1, NN, 256, f1w, 1024, 1024, f1b,
        nullptr, 0, nullptr, (float*)p_ff, 1024, 1);

    // 10. FFN2
    sgemm128<<<dim3(2, (NN + 127) / 128), 256>>>(
        (const float*)p_ff, NN, 1024, f2w, 256, 256, f2b,
        nullptr, 0, nullptr, (float*)p_ff2, 256, 0);

    // 11. LN2(h1 + ff) -> output
    k_ln<<<(NN + 7) / 8, 256>>>((const float*)p_h1, (const float*)p_ff2,
                                ln2_g, ln2_b, out, NN);
}

// round 4
// speedup vs baseline: 3.7952x; 3.7952x over previous
#include <cuda_runtime.h>
#include <math.h>

// Problem constants
#define NN_MAX 50000
#define NE_MAX 400000
#define DIM 256
#define NHEAD 4

// ---------------- scratch (static __device__ arrays, no allocation) -------
__device__ float    g_node_proj[NN_MAX * 768];   // [q|k|v] per node
__device__ float    g_edge_proj[NE_MAX * 768];   // [q|k|v] per edge
__device__ float    g_scores[NE_MAX * NHEAD];    // scores -> ex (in place)
__device__ unsigned g_m[NN_MAX * NHEAD];         // segment max (ordered-uint)
__device__ float    g_denom[NN_MAX * NHEAD];     // segment sum of exp
__device__ float    g_attn_out[NN_MAX * DIM];    // scatter destination
__device__ float    g_tmp[NN_MAX * DIM];         // after Wo
__device__ float    g_h1[NN_MAX * DIM];          // after LN1
__device__ float    g_ff[NN_MAX * 1024];         // after FFN1+gelu
__device__ float    g_ff2[NN_MAX * DIM];         // after FFN2

// ---------------- helpers --------------------------------------------------
__device__ __forceinline__ unsigned f2o(float f) {
    unsigned u = __float_as_uint(f);
    return (u & 0x80000000u) ? ~u : (u | 0x80000000u);
}
__device__ __forceinline__ float o2f(unsigned u) {
    return __uint_as_float((u & 0x80000000u) ? (u & 0x7fffffffu) : ~u);
}
__device__ __forceinline__ float gelu_exact(float x) {
    return 0.5f * x * (1.0f + erff(x * 0.70710678118654752440f));
}
__device__ __forceinline__ float to_tf32(float x) {
    asm("cvt.rna.tf32.f32 %0, %0;" : "+f"(x));
    return x;
}
__device__ __forceinline__ void mma_tf32(float* c, const unsigned* a,
                                         const unsigned* b) {
    asm volatile(
        "mma.sync.aligned.m16n8k8.row.col.f32.tf32.tf32.f32 "
        "{%0,%1,%2,%3}, {%4,%5,%6,%7}, {%8,%9}, {%0,%1,%2,%3};"
        : "+f"(c[0]), "+f"(c[1]), "+f"(c[2]), "+f"(c[3])
        : "r"(a[0]), "r"(a[1]), "r"(a[2]), "r"(a[3]),
          "r"(b[0]), "r"(b[1]));
}

// ---------------- zero scratch --------------------------------------------
__global__ void k_zero(int n_att, int n_md) {
    int i = blockIdx.x * blockDim.x + threadIdx.x;
    if (i < n_att) g_attn_out[i] = 0.0f;
    if (i < n_md) { g_m[i] = 0u; g_denom[i] = 0.0f; }
}

// ---------------- tf32 tensor-core GEMM -----------------------------------
// C[M,N] = A[M,K] @ W (+bias)(+gelu), W split at output col n0 (W0 / W1),
// all col-tile boundaries multiples of 128 so a block sees one weight matrix.
#define BM 128
#define BN 128
#define BK 32
#define ASTR 36    // padded stride: bank = (4*row + k) & 31, conflict-free
#define BSTR 136   // padded stride: bank = (8*k + n) & 31, conflict-free

__global__ __launch_bounds__(256, 2)
void tgemm(const float* __restrict__ A, int M, int K,
           const float* __restrict__ W0, int n0, int ldw0,
           const float* __restrict__ b0,
           const float* __restrict__ W1, int ldw1,
           const float* __restrict__ b1,
           float* __restrict__ C, int N, int act) {
    __shared__ float As[BM][ASTR];   // A[row][k], tf32 bits
    __shared__ float Bs[BK][BSTR];   // B[k][n],  tf32 bits

    const int cb = blockIdx.x * BN;
    const int rb = blockIdx.y * BM;

    const float* W; int ldw; const float* bias;
    if (cb < n0) { W = W0 + cb;        ldw = ldw0; bias = b0 ? b0 + cb        : nullptr; }
    else         { W = W1 + (cb - n0); ldw = ldw1; bias = b1 ? b1 + (cb - n0) : nullptr; }

    const int t    = threadIdx.x;
    const int lane = t & 31;
    const int wid  = t >> 5;
    const int wm   = wid & 1;    // 2 warps along M (64 rows each)
    const int wn   = wid >> 1;   // 4 warps along N (32 cols each)
    const int g    = lane >> 2;  // group id 0..7
    const int tg   = lane & 3;   // thread-in-group 0..3

    float acc[4][4][4];
#pragma unroll
    for (int mt = 0; mt < 4; mt++)
#pragma unroll
        for (int nt = 0; nt < 4; nt++)
#pragma unroll
            for (int r = 0; r < 4; r++) acc[mt][nt][r] = 0.0f;

    for (int k0 = 0; k0 < K; k0 += BK) {
        // stage A: 128 rows x 32 k = 1024 float4 (4 per thread)
#pragma unroll
        for (int it = 0; it < 4; it++) {
            int idx = t + 256 * it;
            int row = idx >> 3;         // 8 float4 per row
            int c4  = (idx & 7) * 4;
            float4 v = make_float4(0.f, 0.f, 0.f, 0.f);
            int grow = rb + row;
            if (grow < M) v = *(const float4*)(A + (size_t)grow * K + k0 + c4);
            As[row][c4 + 0] = to_tf32(v.x);
            As[row][c4 + 1] = to_tf32(v.y);
            As[row][c4 + 2] = to_tf32(v.z);
            As[row][c4 + 3] = to_tf32(v.w);
        }
        // stage B: 32 k-rows x 128 cols = 1024 float4 (4 per thread)
#pragma unroll
        for (int it = 0; it < 4; it++) {
            int idx = t + 256 * it;
            int row = idx >> 5;         // 32 float4 per row
            int c4  = (idx & 31) * 4;
            float4 v = *(const float4*)(W + (size_t)(k0 + row) * ldw + c4);
            Bs[row][c4 + 0] = to_tf32(v.x);
            Bs[row][c4 + 1] = to_tf32(v.y);
            Bs[row][c4 + 2] = to_tf32(v.z);
            Bs[row][c4 + 3] = to_tf32(v.w);
        }
        __syncthreads();

#pragma unroll
        for (int kk = 0; kk < BK; kk += 8) {
            unsigned a[4][4];
#pragma unroll
            for (int mt = 0; mt < 4; mt++) {
                int ar = wm * 64 + mt * 16 + g;
                a[mt][0] = __float_as_uint(As[ar    ][kk + tg    ]);
                a[mt][1] = __float_as_uint(As[ar + 8][kk + tg    ]);
                a[mt][2] = __float_as_uint(As[ar    ][kk + tg + 4]);
                a[mt][3] = __float_as_uint(As[ar + 8][kk + tg + 4]);
            }
            unsigned b[4][2];
#pragma unroll
            for (int nt = 0; nt < 4; nt++) {
                int bc = wn * 32 + nt * 8 + g;
                b[nt][0] = __float_as_uint(Bs[kk + tg    ][bc]);
                b[nt][1] = __float_as_uint(Bs[kk + tg + 4][bc]);
            }
#pragma unroll
            for (int mt = 0; mt < 4; mt++)
#pragma unroll
                for (int nt = 0; nt < 4; nt++)
                    mma_tf32(acc[mt][nt], a[mt], b[nt]);
        }
        __syncthreads();
    }

    // epilogue: c0:(r,c) c1:(r,c+1) c2:(r+8,c) c3:(r+8,c+1), c = 2*tg
#pragma unroll
    for (int mt = 0; mt < 4; mt++) {
        int r0 = rb + wm * 64 + mt * 16 + g;
#pragma unroll
        for (int nt = 0; nt < 4; nt++) {
            int ccol = cb + wn * 32 + nt * 8 + tg * 2;
            int lcol = wn * 32 + nt * 8 + tg * 2;   // bias index (local)
            float v0 = acc[mt][nt][0], v1 = acc[mt][nt][1];
            float v2 = acc[mt][nt][2], v3 = acc[mt][nt][3];
            if (bias) {
                float bb0 = bias[lcol], bb1 = bias[lcol + 1];
                v0 += bb0; v1 += bb1; v2 += bb0; v3 += bb1;
            }
            if (act == 1) {
                v0 = gelu_exact(v0); v1 = gelu_exact(v1);
                v2 = gelu_exact(v2); v3 = gelu_exact(v3);
            }
            if (r0 < M) {
                C[(size_t)r0 * N + ccol]     = v0;
                C[(size_t)r0 * N + ccol + 1] = v1;
            }
            if (r0 + 8 < M) {
                C[(size_t)(r0 + 8) * N + ccol]     = v2;
                C[(size_t)(r0 + 8) * N + ccol + 1] = v3;
            }
        }
    }
}

// ---------------- per-edge scores + segment max ---------------------------
__global__ void k_scores(const int* __restrict__ ei, int NE) {
    int w = (blockIdx.x * blockDim.x + threadIdx.x) >> 5;
    int lane = threadIdx.x & 31;
    if (w >= NE) return;
    int src = ei[w];
    int dst = ei[NE + w];
    const float* qn = g_node_proj + (size_t)src * 768;
    const float* kn = g_node_proj + (size_t)dst * 768 + 256;
    const float* qe = g_edge_proj + (size_t)w * 768;
    const float* ke = qe + 256;
    float ps[4] = {0.f, 0.f, 0.f, 0.f};
#pragma unroll
    for (int j = 0; j < 8; j++) {
        int i = lane + 32 * j;
        float q = qn[i] + qe[i];
        float k = kn[i] + ke[i];
        ps[j >> 1] += q * k;
    }
#pragma unroll
    for (int h = 0; h < 4; h++)
#pragma unroll
        for (int off = 16; off; off >>= 1)
            ps[h] += __shfl_xor_sync(0xffffffffu, ps[h], off);
    if (lane < 4) {
        float s = ps[lane] * 0.125f;  // 1/sqrt(64)
        g_scores[(size_t)w * 4 + lane] = s;
        atomicMax(&g_m[src * 4 + lane], f2o(s));
    }
}

// ---------------- exp + segment sum ---------------------------------------
__global__ void k_expsum(const int* __restrict__ ei, int NE) {
    int i = blockIdx.x * blockDim.x + threadIdx.x;
    if (i >= NE * 4) return;
    int e = i >> 2, h = i & 3;
    int src = ei[e];
    float m = o2f(g_m[src * 4 + h]);
    float ex = expf(g_scores[i] - m);
    g_scores[i] = ex;
    atomicAdd(&g_denom[src * 4 + h], ex);
}

// ---------------- attn * V scatter ----------------------------------------
__global__ void k_scatter(const int* __restrict__ ei, int NE) {
    int w = (blockIdx.x * blockDim.x + threadIdx.x) >> 5;
    int lane = threadIdx.x & 31;
    if (w >= NE) return;
    int src = ei[w];
    int dst = ei[NE + w];
    float attn[4];
#pragma unroll
    for (int h = 0; h < 4; h++)
        attn[h] = g_scores[(size_t)w * 4 + h] / g_denom[src * 4 + h];
    const float* vn = g_node_proj + (size_t)dst * 768 + 512;
    const float* ve = g_edge_proj + (size_t)w * 768 + 512;
    float* o = g_attn_out + (size_t)src * 256;
#pragma unroll
    for (int j = 0; j < 8; j++) {
        int i = lane + 32 * j;
        float v = vn[i] + ve[i];
        atomicAdd(&o[i], attn[j >> 1] * v);
    }
}

// ---------------- layernorm (warp per row of 256) -------------------------
__global__ void k_ln(const float* __restrict__ x, const float* __restrict__ res,
                     const float* __restrict__ g, const float* __restrict__ b,
                     float* __restrict__ out, int M) {
    int w = (blockIdx.x * blockDim.x + threadIdx.x) >> 5;
    int lane = threadIdx.x & 31;
    if (w >= M) return;
    float v[8];
    float s = 0.f;
#pragma unroll
    for (int j = 0; j < 8; j++) {
        int i = lane + 32 * j;
        v[j] = x[(size_t)w * 256 + i] + res[(size_t)w * 256 + i];
        s += v[j];
    }
#pragma unroll
    for (int off = 16; off; off >>= 1) s += __shfl_xor_sync(0xffffffffu, s, off);
    float mu = s * (1.0f / 256.0f);
    float q = 0.f;
#pragma unroll
    for (int j = 0; j < 8; j++) { float d = v[j] - mu; q += d * d; }
#pragma unroll
    for (int off = 16; off; off >>= 1) q += __shfl_xor_sync(0xffffffffu, q, off);
    float rstd = rsqrtf(q * (1.0f / 256.0f) + 1e-5f);
#pragma unroll
    for (int j = 0; j < 8; j++) {
        int i = lane + 32 * j;
        out[(size_t)w * 256 + i] = (v[j] - mu) * rstd * g[i] + b[i];
    }
}

// ---------------- host launch ----------------------------------------------
extern "C" void kernel_launch(void* const* d_in, const int* in_sizes, int n_in,
                              void* d_out, int out_size) {
    const float* h_n   = (const float*)d_in[0];
    const float* h_e   = (const float*)d_in[1];
    const int*   ei    = (const int*)d_in[2];   // int32 (JAX x64 disabled)
    const float* Wq_w  = (const float*)d_in[3];
    const float* Wq_b  = (const float*)d_in[4];
    const float* Wkv_w = (const float*)d_in[5];
    const float* Wkv_b = (const float*)d_in[6];
    const float* Wo_w  = (const float*)d_in[7];
    const float* Wo_b  = (const float*)d_in[8];
    const float* ln1_g = (const float*)d_in[9];
    const float* ln1_b = (const float*)d_in[10];
    const float* f1w   = (const float*)d_in[11];
    const float* f1b   = (const float*)d_in[12];
    const float* f2w   = (const float*)d_in[13];
    const float* f2b   = (const float*)d_in[14];
    const float* ln2_g = (const float*)d_in[15];
    const float* ln2_b = (const float*)d_in[16];
    float* out = (float*)d_out;

    int NN = in_sizes[0] / DIM;
    int NE = in_sizes[1] / DIM;

    void *p_np, *p_ep, *p_att, *p_tmp, *p_h1, *p_ff, *p_ff2;
    cudaGetSymbolAddress(&p_np, g_node_proj);
    cudaGetSymbolAddress(&p_ep, g_edge_proj);
    cudaGetSymbolAddress(&p_att, g_attn_out);
    cudaGetSymbolAddress(&p_tmp, g_tmp);
    cudaGetSymbolAddress(&p_h1, g_h1);
    cudaGetSymbolAddress(&p_ff, g_ff);
    cudaGetSymbolAddress(&p_ff2, g_ff2);

    // 1. zero segment-max / denom / scatter destination
    {
        int n_att = NN * DIM;
        int n_md = NN * NHEAD;
        int n = n_att > n_md ? n_att : n_md;
        k_zero<<<(n + 255) / 256, 256>>>(n_att, n_md);
    }

    // 2. node projections: [q|k|v] = h_n @ [Wq_top | Wkv_top] + biases
    tgemm<<<dim3(6, (NN + 127) / 128), 256>>>(
        h_n, NN, 256, Wq_w, 256, 256, Wq_b, Wkv_w, 512, Wkv_b,
        (float*)p_np, 768, 0);

    // 3. edge projections: [q|k|v] = h_e @ [Wq_bot | Wkv_bot]  (no bias)
    tgemm<<<dim3(6, (NE + 127) / 128), 256>>>(
        h_e, NE, 256, Wq_w + 256 * 256, 256, 256, nullptr,
        Wkv_w + 256 * 512, 512, nullptr,
        (float*)p_ep, 768, 0);

    // 4. per-edge head scores + segment max
    k_scores<<<(NE + 7) / 8, 256>>>(ei, NE);

    // 5. exp + segment sum
    k_expsum<<<(NE * 4 + 255) / 256, 256>>>(ei, NE);

    // 6. attn-weighted V scatter
    k_scatter<<<(NE + 7) / 8, 256>>>(ei, NE);

    // 7. output projection Wo
    tgemm<<<dim3(2, (NN + 127) / 128), 256>>>(
        (const float*)p_att, NN, 256, Wo_w, 256, 256, Wo_b,
        nullptr, 0, nullptr, (float*)p_tmp, 256, 0);

    // 8. LN1(h_n + attn_proj)
    k_ln<<<(NN + 7) / 8, 256>>>(h_n, (const float*)p_tmp, ln1_g, ln1_b,
                                (float*)p_h1, NN);

    // 9. FFN1 + exact GELU
    tgemm<<<dim3(8, (NN + 127) / 128), 256>>>(
        (const float*)p_h1, NN, 256, f1w, 1024, 1024, f1b,
        nullptr, 0, nullptr, (float*)p_ff, 1024, 1);

    // 10. FFN2
    tgemm<<<dim3(2, (NN + 127) / 128), 256>>>(
        (const float*)p_ff, NN, 1024, f2w, 256, 256, f2b,
        nullptr, 0, nullptr, (float*)p_ff2, 256, 0);

    // 11. LN2(h1 + ff) -> output
    k_ln<<<(NN + 7) / 8, 256>>>((const float*)p_h1, (const float*)p_ff2,
                                ln2_g, ln2_b, out, NN);
}

// round 5
// speedup vs baseline: 4.2260x; 1.1135x over previous
#include <cuda_runtime.h>
#include <cuda_bf16.h>
#include <math.h>

// Problem constants
#define NN_MAX 50000
#define NE_MAX 400000
#define DIM 256
#define NHEAD 4

// ---------------- scratch (static __device__ arrays, no allocation) -------
__device__ __nv_bfloat16 g_node_projh[NN_MAX * 768];  // [q|k|v] per node (76.8MB, fits L2)
__device__ __nv_bfloat16 g_edge_projh[NE_MAX * 768];  // [q|k|v] per edge (614MB)
__device__ float    g_scores[NE_MAX * NHEAD];    // scores -> ex (in place)
__device__ unsigned g_m[NN_MAX * NHEAD];         // segment max (ordered-uint)
__device__ float    g_denom[NN_MAX * NHEAD];     // segment sum of exp
__device__ float    g_attn_out[NN_MAX * DIM];    // scatter destination
__device__ float    g_tmp[NN_MAX * DIM];         // after Wo
__device__ float    g_h1[NN_MAX * DIM];          // after LN1
__device__ float    g_ff[NN_MAX * 1024];         // after FFN1+gelu
__device__ float    g_ff2[NN_MAX * DIM];         // after FFN2

// ---------------- helpers --------------------------------------------------
__device__ __forceinline__ unsigned f2o(float f) {
    unsigned u = __float_as_uint(f);
    return (u & 0x80000000u) ? ~u : (u | 0x80000000u);
}
__device__ __forceinline__ float o2f(unsigned u) {
    return __uint_as_float((u & 0x80000000u) ? (u & 0x7fffffffu) : ~u);
}
__device__ __forceinline__ float gelu_exact(float x) {
    return 0.5f * x * (1.0f + erff(x * 0.70710678118654752440f));
}
__device__ __forceinline__ void mma_tf32(float* c, const unsigned* a,
                                         const unsigned* b) {
    asm volatile(
        "mma.sync.aligned.m16n8k8.row.col.f32.tf32.tf32.f32 "
        "{%0,%1,%2,%3}, {%4,%5,%6,%7}, {%8,%9}, {%0,%1,%2,%3};"
        : "+f"(c[0]), "+f"(c[1]), "+f"(c[2]), "+f"(c[3])
        : "r"(a[0]), "r"(a[1]), "r"(a[2]), "r"(a[3]),
          "r"(b[0]), "r"(b[1]));
}
__device__ __forceinline__ void cpa16(unsigned s, const void* g, int sz) {
    asm volatile("cp.async.ca.shared.global [%0], [%1], 16, %2;"
                 :: "r"(s), "l"(g), "r"(sz));
}
__device__ __forceinline__ void cpa_commit() {
    asm volatile("cp.async.commit_group;");
}
template <int N>
__device__ __forceinline__ void cpa_wait() {
    asm volatile("cp.async.wait_group %0;" :: "n"(N));
}

// ---------------- zero scratch --------------------------------------------
__global__ void k_zero(int n_att, int n_md) {
    int i = blockIdx.x * blockDim.x + threadIdx.x;
    if (i < n_att) g_attn_out[i] = 0.0f;
    if (i < n_md) { g_m[i] = 0u; g_denom[i] = 0.0f; }
}

// ---------------- tf32 tensor-core GEMM (cp.async double-buffered) --------
// C[M,N] = A[M,K] @ W (+bias)(+gelu), W split at output col n0 (W0 / W1).
// Output fp32 (obf16=0) or bf16 (obf16=1).
#define BM 128
#define BN 128
#define BK 32
#define ASTR 36    // bank = (4*row + k) & 31, conflict-free
#define BSTR 136   // bank = (8*k + n) & 31, conflict-free
#define A_BUF (BM * ASTR)
#define B_BUF (BK * BSTR)
#define SMEM_BYTES ((2 * A_BUF + 2 * B_BUF) * 4)

__global__ __launch_bounds__(256, 2)
void tgemm(const float* __restrict__ A, int M, int K,
           const float* __restrict__ W0, int n0, int ldw0,
           const float* __restrict__ b0,
           const float* __restrict__ W1, int ldw1,
           const float* __restrict__ b1,
           void* __restrict__ C, int N, int act, int obf16) {
    extern __shared__ float smem[];
    float* As = smem;                  // [2][BM][ASTR]
    float* Bs = smem + 2 * A_BUF;      // [2][BK][BSTR]

    const int cb = blockIdx.x * BN;
    const int rb = blockIdx.y * BM;

    const float* W; int ldw; const float* bias;
    if (cb < n0) { W = W0 + cb;        ldw = ldw0; bias = b0 ? b0 + cb        : nullptr; }
    else         { W = W1 + (cb - n0); ldw = ldw1; bias = b1 ? b1 + (cb - n0) : nullptr; }

    const int t    = threadIdx.x;
    const int lane = t & 31;
    const int wid  = t >> 5;
    const int wm   = wid & 1;    // 2 warps along M (64 rows each)
    const int wn   = wid >> 1;   // 4 warps along N (32 cols each)
    const int g    = lane >> 2;  // group id 0..7
    const int tg   = lane & 3;   // thread-in-group 0..3

    // staging decomposition (per thread: 4 chunks of A, 4 of B)
    const int s_arow = t >> 3;            // 0..31 (+32 per it)
    const int s_ac4  = (t & 7) * 4;
    const int s_brow = t >> 5;            // 0..7  (+8 per it)
    const int s_bc4  = (t & 31) * 4;

    const unsigned as_base = (unsigned)__cvta_generic_to_shared(As);
    const unsigned bs_base = (unsigned)__cvta_generic_to_shared(Bs);

    float acc[4][4][4];
#pragma unroll
    for (int mt = 0; mt < 4; mt++)
#pragma unroll
        for (int nt = 0; nt < 4; nt++)
#pragma unroll
            for (int r = 0; r < 4; r++) acc[mt][nt][r] = 0.0f;

    const int NT = K / BK;

    // ---- stage one tile into buffer `buf` for k-offset k0
    auto stage = [&](int buf, int k0) {
#pragma unroll
        for (int it = 0; it < 4; it++) {
            int row = s_arow + 32 * it;
            int grow = rb + row;
            int ok = (grow < M) ? 16 : 0;
            const float* gp = A + (size_t)(ok ? grow : 0) * K + k0 + s_ac4;
            cpa16(as_base + 4 * (buf * A_BUF + row * ASTR + s_ac4), gp, ok);
        }
#pragma unroll
        for (int it = 0; it < 4; it++) {
            int row = s_brow + 8 * it;
            const float* gp = W + (size_t)(k0 + row) * ldw + s_bc4;
            cpa16(bs_base + 4 * (buf * B_BUF + row * BSTR + s_bc4), gp, 16);
        }
        cpa_commit();
    };

    stage(0, 0);

    for (int kt = 0; kt < NT; kt++) {
        int buf = kt & 1;
        if (kt + 1 < NT) { stage(buf ^ 1, (kt + 1) * BK); cpa_wait<1>(); }
        else             { cpa_wait<0>(); }
        __syncthreads();

        const float* Ab = As + buf * A_BUF;
        const float* Bb = Bs + buf * B_BUF;
#pragma unroll
        for (int kk = 0; kk < BK; kk += 8) {
            unsigned a[4][4];
#pragma unroll
            for (int mt = 0; mt < 4; mt++) {
                int ar = wm * 64 + mt * 16 + g;
                a[mt][0] = __float_as_uint(Ab[(ar    ) * ASTR + kk + tg    ]);
                a[mt][1] = __float_as_uint(Ab[(ar + 8) * ASTR + kk + tg    ]);
                a[mt][2] = __float_as_uint(Ab[(ar    ) * ASTR + kk + tg + 4]);
                a[mt][3] = __float_as_uint(Ab[(ar + 8) * ASTR + kk + tg + 4]);
            }
            unsigned b[4][2];
#pragma unroll
            for (int nt = 0; nt < 4; nt++) {
                int bc = wn * 32 + nt * 8 + g;
                b[nt][0] = __float_as_uint(Bb[(kk + tg    ) * BSTR + bc]);
                b[nt][1] = __float_as_uint(Bb[(kk + tg + 4) * BSTR + bc]);
            }
#pragma unroll
            for (int mt = 0; mt < 4; mt++)
#pragma unroll
                for (int nt = 0; nt < 4; nt++)
                    mma_tf32(acc[mt][nt], a[mt], b[nt]);
        }
        __syncthreads();
    }

    // epilogue: c0:(r,c) c1:(r,c+1) c2:(r+8,c) c3:(r+8,c+1), c = 2*tg
#pragma unroll
    for (int mt = 0; mt < 4; mt++) {
        int r0 = rb + wm * 64 + mt * 16 + g;
#pragma unroll
        for (int nt = 0; nt < 4; nt++) {
            int lcol = wn * 32 + nt * 8 + tg * 2;
            int ccol = cb + lcol;
            float v0 = acc[mt][nt][0], v1 = acc[mt][nt][1];
            float v2 = acc[mt][nt][2], v3 = acc[mt][nt][3];
            if (bias) {
                float bb0 = bias[lcol], bb1 = bias[lcol + 1];
                v0 += bb0; v1 += bb1; v2 += bb0; v3 += bb1;
            }
            if (act == 1) {
                v0 = gelu_exact(v0); v1 = gelu_exact(v1);
                v2 = gelu_exact(v2); v3 = gelu_exact(v3);
            }
            if (obf16) {
                __nv_bfloat16* Cb = (__nv_bfloat16*)C;
                if (r0 < M) {
                    __nv_bfloat162 p;
                    p.x = __float2bfloat16(v0); p.y = __float2bfloat16(v1);
                    *(__nv_bfloat162*)(Cb + (size_t)r0 * N + ccol) = p;
                }
                if (r0 + 8 < M) {
                    __nv_bfloat162 p;
                    p.x = __float2bfloat16(v2); p.y = __float2bfloat16(v3);
                    *(__nv_bfloat162*)(Cb + (size_t)(r0 + 8) * N + ccol) = p;
                }
            } else {
                float* Cf = (float*)C;
                if (r0 < M) {
                    Cf[(size_t)r0 * N + ccol]     = v0;
                    Cf[(size_t)r0 * N + ccol + 1] = v1;
                }
                if (r0 + 8 < M) {
                    Cf[(size_t)(r0 + 8) * N + ccol]     = v2;
                    Cf[(size_t)(r0 + 8) * N + ccol + 1] = v3;
                }
            }
        }
    }
}

// ---------------- per-edge scores + segment max ---------------------------
// one warp per edge; lane l handles 8 contiguous dims [8l, 8l+8); head = l>>3
__device__ __forceinline__ float dot8add(uint4 qa, uint4 qb, uint4 ka, uint4 kb) {
    float s = 0.f;
    const __nv_bfloat162* q1 = (const __nv_bfloat162*)&qa;
    const __nv_bfloat162* q2 = (const __nv_bfloat162*)&qb;
    const __nv_bfloat162* k1 = (const __nv_bfloat162*)&ka;
    const __nv_bfloat162* k2 = (const __nv_bfloat162*)&kb;
#pragma unroll
    for (int j = 0; j < 4; j++) {
        float2 x1 = __bfloat1622float2(q1[j]);
        float2 x2 = __bfloat1622float2(q2[j]);
        float2 y1 = __bfloat1622float2(k1[j]);
        float2 y2 = __bfloat1622float2(k2[j]);
        s += (x1.x + x2.x) * (y1.x + y2.x) + (x1.y + x2.y) * (y1.y + y2.y);
    }
    return s;
}

__global__ void k_scores(const int* __restrict__ ei, int NE) {
    int w = (blockIdx.x * blockDim.x + threadIdx.x) >> 5;
    int lane = threadIdx.x & 31;
    if (w >= NE) return;
    int src = ei[w];
    int dst = ei[NE + w];
    const __nv_bfloat16* qn = g_node_projh + (size_t)src * 768;
    const __nv_bfloat16* kn = g_node_projh + (size_t)dst * 768 + 256;
    const __nv_bfloat16* qe = g_edge_projh + (size_t)w * 768;
    const __nv_bfloat16* ke = qe + 256;
    uint4 a = *(const uint4*)(qn + lane * 8);
    uint4 b = *(const uint4*)(qe + lane * 8);
    uint4 c = *(const uint4*)(kn + lane * 8);
    uint4 d = *(const uint4*)(ke + lane * 8);
    float s = dot8add(a, b, c, d);
#pragma unroll
    for (int off = 1; off < 8; off <<= 1)
        s += __shfl_xor_sync(0xffffffffu, s, off);
    if ((lane & 7) == 0) {
        int h = lane >> 3;
        float sc = s * 0.125f;  // 1/sqrt(64)
        g_scores[(size_t)w * 4 + h] = sc;
        atomicMax(&g_m[src * 4 + h], f2o(sc));
    }
}

// ---------------- exp + segment sum ---------------------------------------
__global__ void k_expsum(const int* __restrict__ ei, int NE) {
    int i = blockIdx.x * blockDim.x + threadIdx.x;
    if (i >= NE * 4) return;
    int e = i >> 2, h = i & 3;
    int src = ei[e];
    float m = o2f(g_m[src * 4 + h]);
    float ex = expf(g_scores[i] - m);
    g_scores[i] = ex;
    atomicAdd(&g_denom[src * 4 + h], ex);
}

// ---------------- attn * V scatter ----------------------------------------
__global__ void k_scatter(const int* __restrict__ ei, int NE) {
    int w = (blockIdx.x * blockDim.x + threadIdx.x) >> 5;
    int lane = threadIdx.x & 31;
    if (w >= NE) return;
    int src = ei[w];
    int dst = ei[NE + w];
    int h = lane >> 3;
    float aw = g_scores[(size_t)w * 4 + h] / g_denom[src * 4 + h];
    const __nv_bfloat16* vn = g_node_projh + (size_t)dst * 768 + 512;
    const __nv_bfloat16* ve = g_edge_projh + (size_t)w * 768 + 512;
    uint4 a = *(const uint4*)(vn + lane * 8);
    uint4 b = *(const uint4*)(ve + lane * 8);
    float* o = g_attn_out + (size_t)src * 256 + lane * 8;
    const __nv_bfloat162* v1 = (const __nv_bfloat162*)&a;
    const __nv_bfloat162* v2 = (const __nv_bfloat162*)&b;
#pragma unroll
    for (int j = 0; j < 4; j++) {
        float2 x1 = __bfloat1622float2(v1[j]);
        float2 x2 = __bfloat1622float2(v2[j]);
        atomicAdd(o + 2 * j,     aw * (x1.x + x2.x));
        atomicAdd(o + 2 * j + 1, aw * (x1.y + x2.y));
    }
}

// ---------------- layernorm (warp per row of 256) -------------------------
__global__ void k_ln(const float* __restrict__ x, const float* __restrict__ res,
                     const float* __restrict__ g, const float* __restrict__ b,
                     float* __restrict__ out, int M) {
    int w = (blockIdx.x * blockDim.x + threadIdx.x) >> 5;
    int lane = threadIdx.x & 31;
    if (w >= M) return;
    float v[8];
    float s = 0.f;
#pragma unroll
    for (int j = 0; j < 8; j++) {
        int i = lane + 32 * j;
        v[j] = x[(size_t)w * 256 + i] + res[(size_t)w * 256 + i];
        s += v[j];
    }
#pragma unroll
    for (int off = 16; off; off >>= 1) s += __shfl_xor_sync(0xffffffffu, s, off);
    float mu = s * (1.0f / 256.0f);
    float q = 0.f;
#pragma unroll
    for (int j = 0; j < 8; j++) { float d = v[j] - mu; q += d * d; }
#pragma unroll
    for (int off = 16; off; off >>= 1) q += __shfl_xor_sync(0xffffffffu, q, off);
    float rstd = rsqrtf(q * (1.0f / 256.0f) + 1e-5f);
#pragma unroll
    for (int j = 0; j < 8; j++) {
        int i = lane + 32 * j;
        out[(size_t)w * 256 + i] = (v[j] - mu) * rstd * g[i] + b[i];
    }
}

// ---------------- host launch ----------------------------------------------
extern "C" void kernel_launch(void* const* d_in, const int* in_sizes, int n_in,
                              void* d_out, int out_size) {
    const float* h_n   = (const float*)d_in[0];
    const float* h_e   = (const float*)d_in[1];
    const int*   ei    = (const int*)d_in[2];   // int32 (JAX x64 disabled)
    const float* Wq_w  = (const float*)d_in[3];
    const float* Wq_b  = (const float*)d_in[4];
    const float* Wkv_w = (const float*)d_in[5];
    const float* Wkv_b = (const float*)d_in[6];
    const float* Wo_w  = (const float*)d_in[7];
    const float* Wo_b  = (const float*)d_in[8];
    const float* ln1_g = (const float*)d_in[9];
    const float* ln1_b = (const float*)d_in[10];
    const float* f1w   = (const float*)d_in[11];
    const float* f1b   = (const float*)d_in[12];
    const float* f2w   = (const float*)d_in[13];
    const float* f2b   = (const float*)d_in[14];
    const float* ln2_g = (const float*)d_in[15];
    const float* ln2_b = (const float*)d_in[16];
    float* out = (float*)d_out;

    int NN = in_sizes[0] / DIM;
    int NE = in_sizes[1] / DIM;

    static int smem_set = 0;
    if (!smem_set) {
        cudaFuncSetAttribute(tgemm, cudaFuncAttributeMaxDynamicSharedMemorySize,
                             SMEM_BYTES);
        smem_set = 1;
    }

    void *p_nph, *p_eph, *p_att, *p_tmp, *p_h1, *p_ff, *p_ff2;
    cudaGetSymbolAddress(&p_nph, g_node_projh);
    cudaGetSymbolAddress(&p_eph, g_edge_projh);
    cudaGetSymbolAddress(&p_att, g_attn_out);
    cudaGetSymbolAddress(&p_tmp, g_tmp);
    cudaGetSymbolAddress(&p_h1, g_h1);
    cudaGetSymbolAddress(&p_ff, g_ff);
    cudaGetSymbolAddress(&p_ff2, g_ff2);

    // 1. zero segment-max / denom / scatter destination
    {
        int n_att = NN * DIM;
        int n_md = NN * NHEAD;
        int n = n_att > n_md ? n_att : n_md;
        k_zero<<<(n + 255) / 256, 256>>>(n_att, n_md);
    }

    // 2. node projections -> bf16 [q|k|v]
    tgemm<<<dim3(6, (NN + 127) / 128), 256, SMEM_BYTES>>>(
        h_n, NN, 256, Wq_w, 256, 256, Wq_b, Wkv_w, 512, Wkv_b,
        p_nph, 768, 0, 1);

    // 3. edge projections -> bf16 [q|k|v] (no bias)
    tgemm<<<dim3(6, (NE + 127) / 128), 256, SMEM_BYTES>>>(
        h_e, NE, 256, Wq_w + 256 * 256, 256, 256, nullptr,
        Wkv_w + 256 * 512, 512, nullptr,
        p_eph, 768, 0, 1);

    // 4. per-edge head scores + segment max
    k_scores<<<(NE + 7) / 8, 256>>>(ei, NE);

    // 5. exp + segment sum
    k_expsum<<<(NE * 4 + 255) / 256, 256>>>(ei, NE);

    // 6. attn-weighted V scatter
    k_scatter<<<(NE + 7) / 8, 256>>>(ei, NE);

    // 7. output projection Wo (fp32 out)
    tgemm<<<dim3(2, (NN + 127) / 128), 256, SMEM_BYTES>>>(
        (const float*)p_att, NN, 256, Wo_w, 256, 256, Wo_b,
        nullptr, 0, nullptr, p_tmp, 256, 0, 0);

    // 8. LN1(h_n + attn_proj)
    k_ln<<<(NN + 7) / 8, 256>>>(h_n, (const float*)p_tmp, ln1_g, ln1_b,
                                (float*)p_h1, NN);

    // 9. FFN1 + exact GELU (fp32 out)
    tgemm<<<dim3(8, (NN + 127) / 128), 256, SMEM_BYTES>>>(
        (const float*)p_h1, NN, 256, f1w, 1024, 1024, f1b,
        nullptr, 0, nullptr, p_ff, 1024, 1, 0);

    // 10. FFN2 (fp32 out)
    tgemm<<<dim3(2, (NN + 127) / 128), 256, SMEM_BYTES>>>(
        (const float*)p_ff, NN, 1024, f2w, 256, 256, f2b,
        nullptr, 0, nullptr, p_ff2, 256, 0, 0);

    // 11. LN2(h1 + ff) -> output
    k_ln<<<(NN + 7) / 8, 256>>>((const float*)p_h1, (const float*)p_ff2,
                                ln2_g, ln2_b, out, NN);
}